// round 14
// baseline (speedup 1.0000x reference)
#include <cuda_runtime.h>
#include <cuda_fp16.h>
#include <cstdint>

#define D_  8
#define NT_ 2048
#define N_  64
#define NH_ 8

// ---------------- device scratch (allocation-free) ----------------
__device__ __align__(16) __half g_Rhi[D_*NT_*N_];
__device__ __align__(16) __half g_Qh [(size_t)D_*NH_*NT_*N_];  // Qr  [bh][u][i] fp16
__device__ __align__(16) __half g_EhT[(size_t)D_*NH_*N_*NT_];  // ErT [bh][i][u] fp16
__device__ __align__(16) float  g_part[(size_t)D_*NH_*NT_*N_]; // [bh][t][i]

// ---------------- helpers ----------------
__device__ __forceinline__ uint32_t smem_u32(const void* p) {
    uint32_t a;
    asm("{ .reg .u64 t; cvta.to.shared.u64 t, %1; cvt.u32.u64 %0, t; }" : "=r"(a) : "l"(p));
    return a;
}
#define SWZ(o) ((o) ^ (((o) >> 3) & 0x70))

#define CP16(s, g) asm volatile("cp.async.ca.shared.global [%0], [%1], 16;" :: "r"(s), "l"(g) : "memory")
#define CP_COMMIT() asm volatile("cp.async.commit_group;" ::: "memory")
#define CP_WAIT2()  asm volatile("cp.async.wait_group 2;" ::: "memory")

__device__ __forceinline__ void ldm4(uint32_t* r, uint32_t addr) {
    asm volatile("ldmatrix.sync.aligned.m8n8.x4.shared.b16 {%0,%1,%2,%3}, [%4];"
        : "=r"(r[0]), "=r"(r[1]), "=r"(r[2]), "=r"(r[3]) : "r"(addr));
}
__device__ __forceinline__ void hmma(float* c, const uint32_t* a, uint32_t b0, uint32_t b1) {
    asm("mma.sync.aligned.m16n8k16.row.col.f32.f16.f16.f32 "
        "{%0,%1,%2,%3},{%4,%5,%6,%7},{%8,%9},{%0,%1,%2,%3};"
        : "+f"(c[0]), "+f"(c[1]), "+f"(c[2]), "+f"(c[3])
        : "r"(a[0]), "r"(a[1]), "r"(a[2]), "r"(a[3]), "r"(b0), "r"(b1));
}
__device__ __forceinline__ uint32_t pack_h2(half2 h) { return *reinterpret_cast<uint32_t*>(&h); }
__device__ __forceinline__ uint32_t f2h2(float f0, float f1) {
    half2 h = __floats2half2_rn(f0, f1);   // f0 -> low half
    return pack_h2(h);
}

// ---------------- K1: fused R-convert + HMMA precompute Qr / ErT ----------------
// smem: Qh [i][j] 8K | Eh [i][j] 8K | Rh [u][j] 16K  (all SW128-swizzled)
// h==0 blocks additionally publish the converted R tile to g_Rhi (full coverage).
#define K1_SQ  0
#define K1_SEH 8192
#define K1_SRH 16384
#define K1_SMEM 32768

__global__ __launch_bounds__(256) void k1_kernel(const float* __restrict__ R,
                                                 const float* __restrict__ Q,
                                                 const float* __restrict__ E) {
    extern __shared__ char sm1[];
    const uint32_t sb = smem_u32(sm1);
    const int tid = threadIdx.x;
    const int b = blockIdx.y, h = blockIdx.z;
    const int u0 = blockIdx.x * 128;
    const int bh = b*NH_ + h;

    // R fp32 tile -> fp16 swizzled smem (and g_Rhi if h==0)
    {
        const float* rsrc = R + ((size_t)b*NT_ + u0)*N_;
        const bool wr = (h == 0);
        for (int p = tid; p < 2048; p += 256) {      // 128 rows x 16 float4
            int row = p >> 4, c4 = p & 15;
            float4 v = *(const float4*)&rsrc[row*N_ + c4*4];
            uint32_t h01 = f2h2(v.x, v.y), h23 = f2h2(v.z, v.w);
            uint32_t off = row*128 + c4*8;
            *(uint2*)(sm1 + K1_SRH + SWZ(off)) = make_uint2(h01, h23);
            if (wr)
                *(uint2*)((char*)g_Rhi + ((size_t)(b*NT_ + u0 + row)*N_ + c4*4)*2) =
                    make_uint2(h01, h23);
        }
    }
    // Q/E fp32 -> fp16 into swizzled smem
    for (int p = tid; p < 64*16; p += 256) {
        int i = p >> 4, q4 = p & 15;
        float4 qv = *(const float4*)&Q[((size_t)h*N_ + i)*N_ + q4*4];
        float4 ev = *(const float4*)&E[((size_t)h*N_ + i)*N_ + q4*4];
        uint32_t off = i*128 + q4*8;
        *(uint2*)(sm1 + K1_SQ  + SWZ(off)) = make_uint2(f2h2(qv.x, qv.y), f2h2(qv.z, qv.w));
        *(uint2*)(sm1 + K1_SEH + SWZ(off)) = make_uint2(f2h2(ev.x, ev.y), f2h2(ev.z, ev.w));
    }
    __syncthreads();

    const int w = tid >> 5, lane = tid & 31;
    const int gid = lane >> 2, tig = lane & 3;
    const int rowA = lane & 15, hi16 = (lane >> 4) << 4;

    if (w < 4) {
        // ---- GEMM A (warps 0-3): Qr[u,i] = sum_j Rh[u,j] * Qh[i,j]
        // warp w: local u-rows [32w, 32w+32) as 2 m-tiles; A-fragments via ldmatrix
        const int url = 32*w;
        uint32_t Ah[2][4][4];
        #pragma unroll
        for (int mt = 0; mt < 2; mt++)
            #pragma unroll
            for (int kk = 0; kk < 4; kk++)
                ldm4(Ah[mt][kk], sb + K1_SRH + SWZ((url + 16*mt + rowA)*128 + 32*kk + hi16));
        float C[2][8][4];
        #pragma unroll
        for (int mt = 0; mt < 2; mt++)
            #pragma unroll
            for (int n = 0; n < 8; n++)
                #pragma unroll
                for (int a = 0; a < 4; a++) C[mt][n][a] = 0.f;
        #pragma unroll
        for (int jj = 0; jj < 4; jj++) {
            uint32_t qh4[4][4];
            #pragma unroll
            for (int kk = 0; kk < 4; kk++)
                ldm4(qh4[kk], sb + K1_SQ + SWZ((16*jj + rowA)*128 + 32*kk + hi16));
            #pragma unroll
            for (int kk = 0; kk < 4; kk++) {
                hmma(C[0][2*jj],   Ah[0][kk], qh4[kk][0], qh4[kk][2]);
                hmma(C[0][2*jj+1], Ah[0][kk], qh4[kk][1], qh4[kk][3]);
                hmma(C[1][2*jj],   Ah[1][kk], qh4[kk][0], qh4[kk][2]);
                hmma(C[1][2*jj+1], Ah[1][kk], qh4[kk][1], qh4[kk][3]);
            }
        }
        #pragma unroll
        for (int mt = 0; mt < 2; mt++) {
            const int uA = u0 + url + 16*mt + gid;
            #pragma unroll
            for (int n = 0; n < 8; n++) {
                int col = 8*n + 2*tig;
                *(uint32_t*)((char*)g_Qh + (((size_t)bh*NT_ + uA    )*N_ + col)*2) = f2h2(C[mt][n][0], C[mt][n][1]);
                *(uint32_t*)((char*)g_Qh + (((size_t)bh*NT_ + uA + 8)*N_ + col)*2) = f2h2(C[mt][n][2], C[mt][n][3]);
            }
        }
    } else {
        // ---- GEMM B (warps 4-7): ErT[i,u] = sum_j Eh[i,j] * Rh[u,j]
        const int w2 = w - 4;
        const int mi = (w2 & 1) * 32;
        const int un = (w2 >> 1) * 64;
        uint32_t Ae[2][4][4];
        #pragma unroll
        for (int mt = 0; mt < 2; mt++)
            #pragma unroll
            for (int kk = 0; kk < 4; kk++)
                ldm4(Ae[mt][kk], sb + K1_SEH + SWZ((mi + 16*mt + rowA)*128 + 32*kk + hi16));
        float C[2][8][4];
        #pragma unroll
        for (int mt = 0; mt < 2; mt++)
            #pragma unroll
            for (int n = 0; n < 8; n++)
                #pragma unroll
                for (int a = 0; a < 4; a++) C[mt][n][a] = 0.f;
        #pragma unroll
        for (int jj = 0; jj < 4; jj++) {
            uint32_t rh4[4][4];
            #pragma unroll
            for (int kk = 0; kk < 4; kk++)
                ldm4(rh4[kk], sb + K1_SRH + SWZ((un + 16*jj + rowA)*128 + 32*kk + hi16));
            #pragma unroll
            for (int kk = 0; kk < 4; kk++) {
                hmma(C[0][2*jj],   Ae[0][kk], rh4[kk][0], rh4[kk][2]);
                hmma(C[0][2*jj+1], Ae[0][kk], rh4[kk][1], rh4[kk][3]);
                hmma(C[1][2*jj],   Ae[1][kk], rh4[kk][0], rh4[kk][2]);
                hmma(C[1][2*jj+1], Ae[1][kk], rh4[kk][1], rh4[kk][3]);
            }
        }
        #pragma unroll
        for (int mt = 0; mt < 2; mt++) {
            const int iA = mi + 16*mt + gid;
            #pragma unroll
            for (int n = 0; n < 8; n++) {
                int col = u0 + un + 8*n + 2*tig;
                *(uint32_t*)((char*)g_EhT + (((size_t)bh*N_ + iA    )*NT_ + col)*2) = f2h2(C[mt][n][0], C[mt][n][1]);
                *(uint32_t*)((char*)g_EhT + (((size_t)bh*N_ + iA + 8)*NT_ + col)*2) = f2h2(C[mt][n][2], C[mt][n][3]);
            }
        }
    }
}

// ---------------- K2: HMMA masked attention core (round-10 champion, verbatim) ----
// 128 threads = 4 warps, TWO m16 tiles per warp; 4-stage cp.async pipeline,
// prefetch distance 3 (ring slots ut&3, +1, +2, +3 all distinct).
#define OFF_QH 0
#define OFF_EH 8192
#define STAGE  16384
#define K2_SMEM (4*STAGE)

__device__ __forceinline__ void load_stage(uint32_t sbase, int bh, int u0, int tid) {
    const char* q_h = (const char*)g_Qh  + (((size_t)bh*NT_ + u0)*N_)*2;
    const char* e_h = (const char*)g_EhT + (((size_t)bh*N_)*NT_ + u0)*2;
    #pragma unroll
    for (int qd = 0; qd < 4; qd++) {
        int c   = tid + qd*128;            // 0..511 16B chunks
        int row = c >> 3, ch = (c & 7) * 16;
        int sw  = SWZ(row*128 + ch);
        CP16(sbase + OFF_QH + sw, q_h + row*128 + ch);
        CP16(sbase + OFF_EH + sw, e_h + (size_t)row*(NT_*2) + ch);
    }
}

__global__ __launch_bounds__(128, 2) void k2_kernel() {
    extern __shared__ char smem[];
    const uint32_t smem_base = smem_u32(smem);
    const int tid  = threadIdx.x;
    const int w    = tid >> 5, lane = tid & 31;
    const int gid  = lane >> 2, tig = lane & 3;
    const int b    = blockIdx.y, x = blockIdx.x;
    const int tt   = 15 - (x >> 3), h = x & 7;     // big tiles first
    const int t0   = tt * 128;
    const int bh   = b*NH_ + h;
    const int trow = t0 + 32*w;                    // this warp's two m16 tiles

    // R A-fragments (registers for whole block)
    uint32_t Ah[2][4][4];
    #pragma unroll
    for (int mt = 0; mt < 2; mt++) {
        size_t r0 = ((size_t)b*NT_ + trow + 16*mt + gid)*N_;
        size_t r1 = r0 + 8*N_;
        #pragma unroll
        for (int kk = 0; kk < 4; kk++) {
            int c0 = 16*kk + 2*tig, c1 = c0 + 8;
            Ah[mt][kk][0] = *(const uint32_t*)((const char*)g_Rhi + (r0 + c0)*2);
            Ah[mt][kk][1] = *(const uint32_t*)((const char*)g_Rhi + (r1 + c0)*2);
            Ah[mt][kk][2] = *(const uint32_t*)((const char*)g_Rhi + (r0 + c1)*2);
            Ah[mt][kk][3] = *(const uint32_t*)((const char*)g_Rhi + (r1 + c1)*2);
        }
    }

    float O[2][8][4];
    #pragma unroll
    for (int mt = 0; mt < 2; mt++)
        #pragma unroll
        for (int n = 0; n < 8; n++)
            #pragma unroll
            for (int a = 0; a < 4; a++) O[mt][n][a] = 0.f;

    const int nU = (tt + 1) * 2;       // >= 2
    load_stage(smem_base, bh, 0, tid);
    CP_COMMIT();
    load_stage(smem_base + STAGE, bh, 64, tid);
    CP_COMMIT();
    if (nU > 2) load_stage(smem_base + 2*STAGE, bh, 128, tid);
    CP_COMMIT();

    const int rowA = lane & 15, hi16 = (lane >> 4) << 4;

    for (int ut = 0; ut < nU; ut++) {
        const int u0 = ut * 64;
        CP_WAIT2();                    // stage ut complete; ut+1, ut+2 may be in flight
        __syncthreads();
        if (ut + 3 < nU)
            load_stage(smem_base + ((ut+3)&3)*STAGE, bh, u0 + 192, tid);
        CP_COMMIT();

        if (u0 <= trow + 31) {         // skip fully-masked diagonal work (warp-uniform)
            const uint32_t sb  = smem_base + (ut&3)*STAGE;
            const uint32_t sQh = sb + OFF_QH, sEh = sb + OFF_EH;

            float S[2][8][4];
            #pragma unroll
            for (int mt = 0; mt < 2; mt++)
                #pragma unroll
                for (int n = 0; n < 8; n++)
                    #pragma unroll
                    for (int a = 0; a < 4; a++) S[mt][n][a] = 0.f;

            // MMA1: S[t,u] = sum_i Rh[t,i] * Qrh[u,i]  (batched ldm4, x4 reuse)
            #pragma unroll
            for (int jj = 0; jj < 4; jj++) {
                uint32_t qh4[4][4];
                #pragma unroll
                for (int kk = 0; kk < 4; kk++)
                    ldm4(qh4[kk], sQh + SWZ((16*jj + rowA)*128 + 32*kk + hi16));
                #pragma unroll
                for (int kk = 0; kk < 4; kk++) {
                    hmma(S[0][2*jj],   Ah[0][kk], qh4[kk][0], qh4[kk][2]);
                    hmma(S[0][2*jj+1], Ah[0][kk], qh4[kk][1], qh4[kk][3]);
                    hmma(S[1][2*jj],   Ah[1][kk], qh4[kk][0], qh4[kk][2]);
                    hmma(S[1][2*jj+1], Ah[1][kk], qh4[kk][1], qh4[kk][3]);
                }
            }

            // causal mask (diagonal-straddling tiles only)
            #pragma unroll
            for (int mt = 0; mt < 2; mt++) {
                if (u0 + 63 > trow + 16*mt) {
                    const int tA = trow + 16*mt + gid, tB = tA + 8;
                    #pragma unroll
                    for (int n = 0; n < 8; n++) {
                        const int uA = u0 + 8*n + 2*tig, uB = uA + 1;
                        if (uA > tA) S[mt][n][0] = 0.f;
                        if (uB > tA) S[mt][n][1] = 0.f;
                        if (uA > tB) S[mt][n][2] = 0.f;
                        if (uB > tB) S[mt][n][3] = 0.f;
                    }
                }
            }

            // MMA2: O[t,i] += Sh[t,u] * ErTh[i,u]  (eh loads issued before convert ALU)
            #pragma unroll
            for (int kk = 0; kk < 4; kk++) {
                uint32_t eh4[4][4];
                #pragma unroll
                for (int jj = 0; jj < 4; jj++)
                    ldm4(eh4[jj], sEh + SWZ((16*jj + rowA)*128 + 32*kk + hi16));
                uint32_t a2h[2][4];
                #pragma unroll
                for (int mt = 0; mt < 2; mt++) {
                    a2h[mt][0] = f2h2(S[mt][2*kk][0],   S[mt][2*kk][1]);
                    a2h[mt][1] = f2h2(S[mt][2*kk][2],   S[mt][2*kk][3]);
                    a2h[mt][2] = f2h2(S[mt][2*kk+1][0], S[mt][2*kk+1][1]);
                    a2h[mt][3] = f2h2(S[mt][2*kk+1][2], S[mt][2*kk+1][3]);
                }
                #pragma unroll
                for (int jj = 0; jj < 4; jj++) {
                    hmma(O[0][2*jj],   a2h[0], eh4[jj][0], eh4[jj][2]);
                    hmma(O[0][2*jj+1], a2h[0], eh4[jj][1], eh4[jj][3]);
                    hmma(O[1][2*jj],   a2h[1], eh4[jj][0], eh4[jj][2]);
                    hmma(O[1][2*jj+1], a2h[1], eh4[jj][1], eh4[jj][3]);
                }
            }
        }
    }

    // store per-h partial
    #pragma unroll
    for (int mt = 0; mt < 2; mt++) {
        const int tA = trow + 16*mt + gid;
        #pragma unroll
        for (int n = 0; n < 8; n++) {
            const int col = 8*n + 2*tig;
            *(float2*)&g_part[((size_t)bh*NT_ + tA    )*N_ + col] = make_float2(O[mt][n][0], O[mt][n][1]);
            *(float2*)&g_part[((size_t)bh*NT_ + tA + 8)*N_ + col] = make_float2(O[mt][n][2], O[mt][n][3]);
        }
    }
}

// ---------------- K3: reduce over h ----------------
__global__ __launch_bounds__(256) void k3_kernel(float* __restrict__ out) {
    const int v = blockIdx.x * 256 + threadIdx.x;
    const int b = v >> 15;
    const int r = v & 32767;
    const float4* p4 = (const float4*)g_part;
    float4 s = make_float4(0.f, 0.f, 0.f, 0.f);
    #pragma unroll
    for (int h = 0; h < NH_; h++) {
        float4 p = p4[((size_t)(b*NH_ + h) << 15) + r];
        s.x += p.x; s.y += p.y; s.z += p.z; s.w += p.w;
    }
    ((float4*)out)[v] = s;
}

extern "C" void kernel_launch(void* const* d_in, const int* in_sizes, int n_in,
                              void* d_out, int out_size) {
    const float* R = (const float*)d_in[0];
    const float* Q = (const float*)d_in[1];
    const float* E = (const float*)d_in[2];
    float* out = (float*)d_out;

    cudaFuncSetAttribute(k1_kernel, cudaFuncAttributeMaxDynamicSharedMemorySize, K1_SMEM);
    cudaFuncSetAttribute(k2_kernel, cudaFuncAttributeMaxDynamicSharedMemorySize, K2_SMEM);

    k1_kernel<<<dim3(16, D_, NH_), 256, K1_SMEM>>>(R, Q, E);
    k2_kernel<<<dim3(128, D_), 128, K2_SMEM>>>();
    k3_kernel<<<(D_*NT_*N_/4) / 256, 256>>>(out);
}

// round 15
// speedup vs baseline: 1.0851x; 1.0851x over previous
#include <cuda_runtime.h>
#include <cuda_fp16.h>
#include <cstdint>

#define D_  8
#define NT_ 2048
#define N_  64
#define NH_ 8

// ---------------- device scratch (allocation-free) ----------------
__device__ __align__(16) __half g_Rhi[D_*NT_*N_];
__device__ __align__(16) __half g_Qh [(size_t)D_*NH_*NT_*N_];  // Qr  [bh][u][i] fp16
__device__ __align__(16) __half g_EhT[(size_t)D_*NH_*N_*NT_];  // ErT [bh][i][u] fp16
__device__ __align__(16) __half g_part[(size_t)D_*NH_*NT_*N_]; // [bh][t][i] fp16 partials

// ---------------- helpers ----------------
__device__ __forceinline__ uint32_t smem_u32(const void* p) {
    uint32_t a;
    asm("{ .reg .u64 t; cvta.to.shared.u64 t, %1; cvt.u32.u64 %0, t; }" : "=r"(a) : "l"(p));
    return a;
}
#define SWZ(o) ((o) ^ (((o) >> 3) & 0x70))

#define CP16(s, g) asm volatile("cp.async.ca.shared.global [%0], [%1], 16;" :: "r"(s), "l"(g) : "memory")
#define CP_COMMIT() asm volatile("cp.async.commit_group;" ::: "memory")
#define CP_WAIT2()  asm volatile("cp.async.wait_group 2;" ::: "memory")
#define CP_WAIT0()  asm volatile("cp.async.wait_group 0;" ::: "memory")

__device__ __forceinline__ void ldm4(uint32_t* r, uint32_t addr) {
    asm volatile("ldmatrix.sync.aligned.m8n8.x4.shared.b16 {%0,%1,%2,%3}, [%4];"
        : "=r"(r[0]), "=r"(r[1]), "=r"(r[2]), "=r"(r[3]) : "r"(addr));
}
__device__ __forceinline__ void hmma(float* c, const uint32_t* a, uint32_t b0, uint32_t b1) {
    asm("mma.sync.aligned.m16n8k16.row.col.f32.f16.f16.f32 "
        "{%0,%1,%2,%3},{%4,%5,%6,%7},{%8,%9},{%0,%1,%2,%3};"
        : "+f"(c[0]), "+f"(c[1]), "+f"(c[2]), "+f"(c[3])
        : "r"(a[0]), "r"(a[1]), "r"(a[2]), "r"(a[3]), "r"(b0), "r"(b1));
}
__device__ __forceinline__ uint32_t pack_h2(half2 h) { return *reinterpret_cast<uint32_t*>(&h); }
__device__ __forceinline__ uint32_t f2h2(float f0, float f1) {
    half2 h = __floats2half2_rn(f0, f1);   // f0 -> low half
    return pack_h2(h);
}

// ---------------- K0: round R to fp16 ----------------
__global__ __launch_bounds__(256) void k0_kernel(const float* __restrict__ R) {
    const int idx = blockIdx.x * 256 + threadIdx.x;       // 262144 float4s
    float4 v = ((const float4*)R)[idx];
    ((uint2*)g_Rhi)[idx] = make_uint2(f2h2(v.x, v.y), f2h2(v.z, v.w));
}

// ---------------- K1: HMMA precompute Qr[u,i] and ErT[i,u] (fp16, single-product) ----
#define K1_SQ  0
#define K1_SEH 8192
#define K1_SRH 16384
#define K1_SMEM 32768

__global__ __launch_bounds__(256) void k1_kernel(const float* __restrict__ Q,
                                                 const float* __restrict__ E) {
    extern __shared__ char sm1[];
    const uint32_t sb = smem_u32(sm1);
    const int tid = threadIdx.x;
    const int b = blockIdx.y, h = blockIdx.z;
    const int u0 = blockIdx.x * 128;
    const int bh = b*NH_ + h;

    {   // stage Rh tile (128 rows x 128B) via cp.async, swizzled
        const char* rh = (const char*)g_Rhi + ((size_t)(b*NT_ + u0) * N_) * 2;
        #pragma unroll
        for (int qd = 0; qd < 4; qd++) {
            int c = tid + qd*256;                 // 0..1023 16B chunks
            int row = c >> 3, ch = (c & 7) * 16;
            CP16(sb + K1_SRH + SWZ(row*128 + ch), rh + row*128 + ch);
        }
        CP_COMMIT();
    }
    // Q/E fp32 -> fp16 into swizzled smem
    for (int p = tid; p < 64*16; p += 256) {
        int i = p >> 4, q4 = p & 15;
        float4 qv = *(const float4*)&Q[((size_t)h*N_ + i)*N_ + q4*4];
        float4 ev = *(const float4*)&E[((size_t)h*N_ + i)*N_ + q4*4];
        uint32_t off = i*128 + q4*8;
        uint32_t sw0 = SWZ(off), sw1 = SWZ(off + 4);
        *(uint32_t*)(sm1 + K1_SQ  + sw0) = f2h2(qv.x, qv.y);
        *(uint32_t*)(sm1 + K1_SQ  + sw1) = f2h2(qv.z, qv.w);
        *(uint32_t*)(sm1 + K1_SEH + sw0) = f2h2(ev.x, ev.y);
        *(uint32_t*)(sm1 + K1_SEH + sw1) = f2h2(ev.z, ev.w);
    }
    CP_WAIT0();
    __syncthreads();

    const int w = tid >> 5, lane = tid & 31;
    const int gid = lane >> 2, tig = lane & 3;
    const int rowA = lane & 15, hi16 = (lane >> 4) << 4;

    if (w < 4) {
        // ---- GEMM A (warps 0-3): Qr[u,i] = sum_j Rh[u,j] * Qh[i,j]
        const int urow = u0 + 32*w;
        uint32_t Ah[2][4][4];
        #pragma unroll
        for (int mt = 0; mt < 2; mt++) {
            size_t r0 = ((size_t)b*NT_ + urow + 16*mt + gid)*N_;
            size_t r1 = r0 + 8*N_;
            #pragma unroll
            for (int kk = 0; kk < 4; kk++) {
                int c0 = 16*kk + 2*tig, c1 = c0 + 8;
                Ah[mt][kk][0] = *(const uint32_t*)((const char*)g_Rhi + (r0 + c0)*2);
                Ah[mt][kk][1] = *(const uint32_t*)((const char*)g_Rhi + (r1 + c0)*2);
                Ah[mt][kk][2] = *(const uint32_t*)((const char*)g_Rhi + (r0 + c1)*2);
                Ah[mt][kk][3] = *(const uint32_t*)((const char*)g_Rhi + (r1 + c1)*2);
            }
        }
        float C[2][8][4];
        #pragma unroll
        for (int mt = 0; mt < 2; mt++)
            #pragma unroll
            for (int n = 0; n < 8; n++)
                #pragma unroll
                for (int a = 0; a < 4; a++) C[mt][n][a] = 0.f;
        #pragma unroll
        for (int jj = 0; jj < 4; jj++) {
            uint32_t qh4[4][4];
            #pragma unroll
            for (int kk = 0; kk < 4; kk++)
                ldm4(qh4[kk], sb + K1_SQ + SWZ((16*jj + rowA)*128 + 32*kk + hi16));
            #pragma unroll
            for (int kk = 0; kk < 4; kk++) {
                hmma(C[0][2*jj],   Ah[0][kk], qh4[kk][0], qh4[kk][2]);
                hmma(C[0][2*jj+1], Ah[0][kk], qh4[kk][1], qh4[kk][3]);
                hmma(C[1][2*jj],   Ah[1][kk], qh4[kk][0], qh4[kk][2]);
                hmma(C[1][2*jj+1], Ah[1][kk], qh4[kk][1], qh4[kk][3]);
            }
        }
        #pragma unroll
        for (int mt = 0; mt < 2; mt++) {
            const int uA = urow + 16*mt + gid;
            #pragma unroll
            for (int n = 0; n < 8; n++) {
                int col = 8*n + 2*tig;
                *(uint32_t*)((char*)g_Qh + (((size_t)bh*NT_ + uA    )*N_ + col)*2) = f2h2(C[mt][n][0], C[mt][n][1]);
                *(uint32_t*)((char*)g_Qh + (((size_t)bh*NT_ + uA + 8)*N_ + col)*2) = f2h2(C[mt][n][2], C[mt][n][3]);
            }
        }
    } else {
        // ---- GEMM B (warps 4-7): ErT[i,u] = sum_j Eh[i,j] * Rh[u,j]
        const int w2 = w - 4;
        const int mi = (w2 & 1) * 32;
        const int un = (w2 >> 1) * 64;
        uint32_t Ae[2][4][4];
        #pragma unroll
        for (int mt = 0; mt < 2; mt++)
            #pragma unroll
            for (int kk = 0; kk < 4; kk++)
                ldm4(Ae[mt][kk], sb + K1_SEH + SWZ((mi + 16*mt + rowA)*128 + 32*kk + hi16));
        float C[2][8][4];
        #pragma unroll
        for (int mt = 0; mt < 2; mt++)
            #pragma unroll
            for (int n = 0; n < 8; n++)
                #pragma unroll
                for (int a = 0; a < 4; a++) C[mt][n][a] = 0.f;
        #pragma unroll
        for (int jj = 0; jj < 4; jj++) {
            uint32_t rh4[4][4];
            #pragma unroll
            for (int kk = 0; kk < 4; kk++)
                ldm4(rh4[kk], sb + K1_SRH + SWZ((un + 16*jj + rowA)*128 + 32*kk + hi16));
            #pragma unroll
            for (int kk = 0; kk < 4; kk++) {
                hmma(C[0][2*jj],   Ae[0][kk], rh4[kk][0], rh4[kk][2]);
                hmma(C[0][2*jj+1], Ae[0][kk], rh4[kk][1], rh4[kk][3]);
                hmma(C[1][2*jj],   Ae[1][kk], rh4[kk][0], rh4[kk][2]);
                hmma(C[1][2*jj+1], Ae[1][kk], rh4[kk][1], rh4[kk][3]);
            }
        }
        #pragma unroll
        for (int mt = 0; mt < 2; mt++) {
            const int iA = mi + 16*mt + gid;
            #pragma unroll
            for (int n = 0; n < 8; n++) {
                int col = u0 + un + 8*n + 2*tig;
                *(uint32_t*)((char*)g_EhT + (((size_t)bh*N_ + iA    )*NT_ + col)*2) = f2h2(C[mt][n][0], C[mt][n][1]);
                *(uint32_t*)((char*)g_EhT + (((size_t)bh*N_ + iA + 8)*NT_ + col)*2) = f2h2(C[mt][n][2], C[mt][n][3]);
            }
        }
    }
}

// ---------------- K2: HMMA masked attention core ----------------
// 128 threads = 4 warps, TWO m16 tiles per warp; 4-stage cp.async pipeline,
// prefetch distance 3 (ring slots ut&3, +1, +2, +3 all distinct).
#define OFF_QH 0
#define OFF_EH 8192
#define STAGE  16384
#define K2_SMEM (4*STAGE)

__device__ __forceinline__ void load_stage(uint32_t sbase, int bh, int u0, int tid) {
    const char* q_h = (const char*)g_Qh  + (((size_t)bh*NT_ + u0)*N_)*2;
    const char* e_h = (const char*)g_EhT + (((size_t)bh*N_)*NT_ + u0)*2;
    #pragma unroll
    for (int qd = 0; qd < 4; qd++) {
        int c   = tid + qd*128;            // 0..511 16B chunks
        int row = c >> 3, ch = (c & 7) * 16;
        int sw  = SWZ(row*128 + ch);
        CP16(sbase + OFF_QH + sw, q_h + row*128 + ch);
        CP16(sbase + OFF_EH + sw, e_h + (size_t)row*(NT_*2) + ch);
    }
}

__global__ __launch_bounds__(128, 2) void k2_kernel() {
    extern __shared__ char smem[];
    const uint32_t smem_base = smem_u32(smem);
    const int tid  = threadIdx.x;
    const int w    = tid >> 5, lane = tid & 31;
    const int gid  = lane >> 2, tig = lane & 3;
    const int b    = blockIdx.y, x = blockIdx.x;
    const int tt   = 15 - (x >> 3), h = x & 7;     // big tiles first
    const int t0   = tt * 128;
    const int bh   = b*NH_ + h;
    const int trow = t0 + 32*w;                    // this warp's two m16 tiles

    // R A-fragments (registers for whole block)
    uint32_t Ah[2][4][4];
    #pragma unroll
    for (int mt = 0; mt < 2; mt++) {
        size_t r0 = ((size_t)b*NT_ + trow + 16*mt + gid)*N_;
        size_t r1 = r0 + 8*N_;
        #pragma unroll
        for (int kk = 0; kk < 4; kk++) {
            int c0 = 16*kk + 2*tig, c1 = c0 + 8;
            Ah[mt][kk][0] = *(const uint32_t*)((const char*)g_Rhi + (r0 + c0)*2);
            Ah[mt][kk][1] = *(const uint32_t*)((const char*)g_Rhi + (r1 + c0)*2);
            Ah[mt][kk][2] = *(const uint32_t*)((const char*)g_Rhi + (r0 + c1)*2);
            Ah[mt][kk][3] = *(const uint32_t*)((const char*)g_Rhi + (r1 + c1)*2);
        }
    }

    float O[2][8][4];
    #pragma unroll
    for (int mt = 0; mt < 2; mt++)
        #pragma unroll
        for (int n = 0; n < 8; n++)
            #pragma unroll
            for (int a = 0; a < 4; a++) O[mt][n][a] = 0.f;

    const int nU = (tt + 1) * 2;       // >= 2
    load_stage(smem_base, bh, 0, tid);
    CP_COMMIT();
    load_stage(smem_base + STAGE, bh, 64, tid);
    CP_COMMIT();
    if (nU > 2) load_stage(smem_base + 2*STAGE, bh, 128, tid);
    CP_COMMIT();

    const int rowA = lane & 15, hi16 = (lane >> 4) << 4;

    for (int ut = 0; ut < nU; ut++) {
        const int u0 = ut * 64;
        CP_WAIT2();                    // stage ut complete; ut+1, ut+2 may be in flight
        __syncthreads();
        if (ut + 3 < nU)
            load_stage(smem_base + ((ut+3)&3)*STAGE, bh, u0 + 192, tid);
        CP_COMMIT();

        if (u0 <= trow + 31) {         // skip fully-masked diagonal work (warp-uniform)
            const uint32_t sb  = smem_base + (ut&3)*STAGE;
            const uint32_t sQh = sb + OFF_QH, sEh = sb + OFF_EH;

            float S[2][8][4];
            #pragma unroll
            for (int mt = 0; mt < 2; mt++)
                #pragma unroll
                for (int n = 0; n < 8; n++)
                    #pragma unroll
                    for (int a = 0; a < 4; a++) S[mt][n][a] = 0.f;

            // MMA1: S[t,u] = sum_i Rh[t,i] * Qrh[u,i]  (batched ldm4, x4 reuse)
            #pragma unroll
            for (int jj = 0; jj < 4; jj++) {
                uint32_t qh4[4][4];
                #pragma unroll
                for (int kk = 0; kk < 4; kk++)
                    ldm4(qh4[kk], sQh + SWZ((16*jj + rowA)*128 + 32*kk + hi16));
                #pragma unroll
                for (int kk = 0; kk < 4; kk++) {
                    hmma(S[0][2*jj],   Ah[0][kk], qh4[kk][0], qh4[kk][2]);
                    hmma(S[0][2*jj+1], Ah[0][kk], qh4[kk][1], qh4[kk][3]);
                    hmma(S[1][2*jj],   Ah[1][kk], qh4[kk][0], qh4[kk][2]);
                    hmma(S[1][2*jj+1], Ah[1][kk], qh4[kk][1], qh4[kk][3]);
                }
            }

            // causal mask (diagonal-straddling tiles only)
            #pragma unroll
            for (int mt = 0; mt < 2; mt++) {
                if (u0 + 63 > trow + 16*mt) {
                    const int tA = trow + 16*mt + gid, tB = tA + 8;
                    #pragma unroll
                    for (int n = 0; n < 8; n++) {
                        const int uA = u0 + 8*n + 2*tig, uB = uA + 1;
                        if (uA > tA) S[mt][n][0] = 0.f;
                        if (uB > tA) S[mt][n][1] = 0.f;
                        if (uA > tB) S[mt][n][2] = 0.f;
                        if (uB > tB) S[mt][n][3] = 0.f;
                    }
                }
            }

            // MMA2: O[t,i] += Sh[t,u] * ErTh[i,u]  (eh loads issued before convert ALU)
            #pragma unroll
            for (int kk = 0; kk < 4; kk++) {
                uint32_t eh4[4][4];
                #pragma unroll
                for (int jj = 0; jj < 4; jj++)
                    ldm4(eh4[jj], sEh + SWZ((16*jj + rowA)*128 + 32*kk + hi16));
                uint32_t a2h[2][4];
                #pragma unroll
                for (int mt = 0; mt < 2; mt++) {
                    a2h[mt][0] = f2h2(S[mt][2*kk][0],   S[mt][2*kk][1]);
                    a2h[mt][1] = f2h2(S[mt][2*kk][2],   S[mt][2*kk][3]);
                    a2h[mt][2] = f2h2(S[mt][2*kk+1][0], S[mt][2*kk+1][1]);
                    a2h[mt][3] = f2h2(S[mt][2*kk+1][2], S[mt][2*kk+1][3]);
                }
                #pragma unroll
                for (int jj = 0; jj < 4; jj++) {
                    hmma(O[0][2*jj],   a2h[0], eh4[jj][0], eh4[jj][2]);
                    hmma(O[0][2*jj+1], a2h[0], eh4[jj][1], eh4[jj][3]);
                    hmma(O[1][2*jj],   a2h[1], eh4[jj][0], eh4[jj][2]);
                    hmma(O[1][2*jj+1], a2h[1], eh4[jj][1], eh4[jj][3]);
                }
            }
        }
    }

    // store per-h partial (fp16-packed: halves g_part traffic)
    #pragma unroll
    for (int mt = 0; mt < 2; mt++) {
        const int tA = trow + 16*mt + gid;
        #pragma unroll
        for (int n = 0; n < 8; n++) {
            const int col = 8*n + 2*tig;
            *(uint32_t*)((char*)g_part + (((size_t)bh*NT_ + tA    )*N_ + col)*2) = f2h2(O[mt][n][0], O[mt][n][1]);
            *(uint32_t*)((char*)g_part + (((size_t)bh*NT_ + tA + 8)*N_ + col)*2) = f2h2(O[mt][n][2], O[mt][n][3]);
        }
    }
}

// ---------------- K3: reduce over h (fp16 partials -> fp32 out) ----------------
__global__ __launch_bounds__(256) void k3_kernel(float* __restrict__ out) {
    const int v = blockIdx.x * 256 + threadIdx.x;    // output float4 index, 262144 total
    const int b = v >> 15;
    const int r = v & 32767;
    const uint2* p2 = (const uint2*)g_part;          // 4 halves per uint2
    float4 s = make_float4(0.f, 0.f, 0.f, 0.f);
    #pragma unroll
    for (int h = 0; h < NH_; h++) {
        uint2 p = p2[((size_t)(b*NH_ + h) << 15) + r];
        half2 h01 = *reinterpret_cast<half2*>(&p.x);
        half2 h23 = *reinterpret_cast<half2*>(&p.y);
        float2 f01 = __half22float2(h01);
        float2 f23 = __half22float2(h23);
        s.x += f01.x; s.y += f01.y; s.z += f23.x; s.w += f23.y;
    }
    ((float4*)out)[v] = s;
}

extern "C" void kernel_launch(void* const* d_in, const int* in_sizes, int n_in,
                              void* d_out, int out_size) {
    const float* R = (const float*)d_in[0];
    const float* Q = (const float*)d_in[1];
    const float* E = (const float*)d_in[2];
    float* out = (float*)d_out;

    cudaFuncSetAttribute(k1_kernel, cudaFuncAttributeMaxDynamicSharedMemorySize, K1_SMEM);
    cudaFuncSetAttribute(k2_kernel, cudaFuncAttributeMaxDynamicSharedMemorySize, K2_SMEM);

    k0_kernel<<<1024, 256>>>(R);
    k1_kernel<<<dim3(16, D_, NH_), 256, K1_SMEM>>>(Q, E);
    k2_kernel<<<dim3(128, D_), 128, K2_SMEM>>>();
    k3_kernel<<<(D_*NT_*N_/4) / 256, 256>>>(out);
}